// round 6
// baseline (speedup 1.0000x reference)
#include <cuda_runtime.h>
#include <cuda_fp16.h>

#define NN 100000
#define FD 32
#define NPW 8

// Scratch (static device globals — no allocation in kernel_launch)
__device__ __half g_sc[NN * FD];    // message values (fp16), gather side
__device__ float  g_agg[NN * FD];   // fp32 accumulator, seeded with self-loop
__device__ float  g_dinv[NN];
__device__ int    g_deg[NN];

__global__ void k_init_deg() {
    int i = blockIdx.x * blockDim.x + threadIdx.x;
    if (i < NN) g_deg[i] = 1;  // self-loop contributes 1
}

__global__ void k_count(const int* __restrict__ dst, int E) {
    int t = blockIdx.x * blockDim.x + threadIdx.x;
    int e = t * 4;
    if (e + 3 < E) {
        int4 d = *reinterpret_cast<const int4*>(dst + e);
        atomicAdd(&g_deg[d.x], 1);
        atomicAdd(&g_deg[d.y], 1);
        atomicAdd(&g_deg[d.z], 1);
        atomicAdd(&g_deg[d.w], 1);
    } else {
        for (int i = e; i < E; i++) atomicAdd(&g_deg[dst[i]], 1);
    }
}

__global__ void k_dinv() {
    int i = blockIdx.x * blockDim.x + threadIdx.x;
    if (i < NN) g_dinv[i] = rsqrtf((float)g_deg[i]);
}

// s0 = dinv * x  (pure streaming; no GEMV before scatter anymore).
// Writes fp16 messages + seeds fp32 accumulator (self-loop term).
__global__ void k_scale0(const float* __restrict__ x) {
    int g = blockIdx.x * blockDim.x + threadIdx.x;   // one float4 per thread
    if (g >= NN * FD / 4) return;
    int node = g >> 3;
    float dv = g_dinv[node];
    float4 v = *reinterpret_cast<const float4*>(x + (size_t)g * 4);
    v.x *= dv; v.y *= dv; v.z *= dv; v.w *= dv;
    *reinterpret_cast<float4*>(g_agg + (size_t)g * 4) = v;
    __half2 p0 = __floats2half2_rn(v.x, v.y);
    __half2 p1 = __floats2half2_rn(v.z, v.w);
    uint2 packed;
    packed.x = *reinterpret_cast<unsigned int*>(&p0);
    packed.y = *reinterpret_cast<unsigned int*>(&p1);
    *reinterpret_cast<uint2*>(g_sc + (size_t)g * 4) = packed;
}

// Scatter: 4 lanes per edge. Lane loads 8 fp16 msgs (16B), converts,
// issues two red.global.add.v4.f32 (32B) into the fp32 accumulator.
__global__ __launch_bounds__(256) void k_scatter(const int* __restrict__ src,
                                                 const int* __restrict__ dst,
                                                 int E) {
    long long t = (long long)blockIdx.x * 256 + threadIdx.x;
    int e = (int)(t >> 2);
    if (e >= E) return;
    int q = ((int)t & 3) << 3;   // feature offset 0,8,16,24

    int s = src[e];
    int d = dst[e];

    uint4 raw = *reinterpret_cast<const uint4*>(g_sc + (size_t)s * FD + q);
    __half2 h01 = *reinterpret_cast<__half2*>(&raw.x);
    __half2 h23 = *reinterpret_cast<__half2*>(&raw.y);
    __half2 h45 = *reinterpret_cast<__half2*>(&raw.z);
    __half2 h67 = *reinterpret_cast<__half2*>(&raw.w);
    float2 f01 = __half22float2(h01);
    float2 f23 = __half22float2(h23);
    float2 f45 = __half22float2(h45);
    float2 f67 = __half22float2(h67);

    float* a = g_agg + (size_t)d * FD + q;
    asm volatile("red.global.add.v4.f32 [%0], {%1, %2, %3, %4};"
                 :: "l"(a), "f"(f01.x), "f"(f01.y), "f"(f23.x), "f"(f23.y)
                 : "memory");
    asm volatile("red.global.add.v4.f32 [%0], {%1, %2, %3, %4};"
                 :: "l"(a + 4), "f"(f45.x), "f"(f45.y), "f"(f67.x), "f"(f67.y)
                 : "memory");
}

// Mid: Ph0 = dinv*agg0; h1 = relu(Ph0 @ W0 + b0); s1 = dinv*h1.
// Overwrites g_agg with s1 (seed for next scatter) and g_sc with fp16(s1).
__global__ __launch_bounds__(256) void k_mid(const float* __restrict__ W0,
                                             const float* __restrict__ b0) {
    __shared__ float Ws[FD * FD];
    __shared__ float s_row[8][FD];
    int tid = threadIdx.x;
    int lane = tid & 31;
    int wb = tid >> 5;
    #pragma unroll
    for (int i = tid; i < FD * FD; i += 256) Ws[i] = W0[i];
    __syncthreads();

    float Wc[FD];
    #pragma unroll
    for (int k = 0; k < FD; k++) Wc[k] = Ws[k * FD + lane];  // conflict-free LDS
    float bl = b0[lane];

    int base = (blockIdx.x * 8 + wb) * NPW;
    if (base >= NN) return;

    #pragma unroll
    for (int u = 0; u < NPW; u++) {
        int node = base + u;
        float dv = g_dinv[node];
        float ph = dv * g_agg[(size_t)node * FD + lane];   // coalesced
        s_row[wb][lane] = ph;
        __syncwarp();
        const float4* r = reinterpret_cast<const float4*>(s_row[wb]);
        float acc = 0.0f;
        #pragma unroll
        for (int j = 0; j < FD / 4; j++) {
            float4 v = r[j];                                // broadcast LDS.128
            acc = fmaf(v.x, Wc[4 * j + 0], acc);
            acc = fmaf(v.y, Wc[4 * j + 1], acc);
            acc = fmaf(v.z, Wc[4 * j + 2], acc);
            acc = fmaf(v.w, Wc[4 * j + 3], acc);
        }
        __syncwarp();
        float h = fmaxf(acc + bl, 0.0f);
        float s1 = dv * h;
        g_agg[(size_t)node * FD + lane] = s1;
        g_sc[(size_t)node * FD + lane] = __float2half(s1);
    }
}

// Final: Ph1 = dinv*agg1; h2 = relu(Ph1 @ W1 + b1); out = h2 @ Wf + bf.
__global__ __launch_bounds__(256) void k_final(const float* __restrict__ W1,
                                               const float* __restrict__ b1,
                                               const float* __restrict__ Wf,
                                               const float* __restrict__ bf,
                                               float* __restrict__ out) {
    __shared__ float Ws1[FD * FD];
    __shared__ float Wsf[FD * FD];
    __shared__ float s_row[8][FD];
    int tid = threadIdx.x;
    int lane = tid & 31;
    int wb = tid >> 5;
    #pragma unroll
    for (int i = tid; i < FD * FD; i += 256) { Ws1[i] = W1[i]; Wsf[i] = Wf[i]; }
    __syncthreads();

    float Wc1[FD], Wcf[FD];
    #pragma unroll
    for (int k = 0; k < FD; k++) { Wc1[k] = Ws1[k * FD + lane]; Wcf[k] = Wsf[k * FD + lane]; }
    float b1l = b1[lane];
    float bfl = bf[lane];

    int base = (blockIdx.x * 8 + wb) * NPW;
    if (base >= NN) return;

    #pragma unroll
    for (int u = 0; u < NPW; u++) {
        int node = base + u;
        float dv = g_dinv[node];
        float ph = dv * g_agg[(size_t)node * FD + lane];
        s_row[wb][lane] = ph;
        __syncwarp();
        const float4* r = reinterpret_cast<const float4*>(s_row[wb]);
        float acc = 0.0f;
        #pragma unroll
        for (int j = 0; j < FD / 4; j++) {
            float4 v = r[j];
            acc = fmaf(v.x, Wc1[4 * j + 0], acc);
            acc = fmaf(v.y, Wc1[4 * j + 1], acc);
            acc = fmaf(v.z, Wc1[4 * j + 2], acc);
            acc = fmaf(v.w, Wc1[4 * j + 3], acc);
        }
        __syncwarp();
        float h2 = fmaxf(acc + b1l, 0.0f);
        s_row[wb][lane] = h2;
        __syncwarp();
        float acc2 = bfl;
        #pragma unroll
        for (int j = 0; j < FD / 4; j++) {
            float4 v = r[j];
            acc2 = fmaf(v.x, Wcf[4 * j + 0], acc2);
            acc2 = fmaf(v.y, Wcf[4 * j + 1], acc2);
            acc2 = fmaf(v.z, Wcf[4 * j + 2], acc2);
            acc2 = fmaf(v.w, Wcf[4 * j + 3], acc2);
        }
        __syncwarp();
        out[(size_t)node * FD + lane] = acc2;
    }
}

extern "C" void kernel_launch(void* const* d_in, const int* in_sizes, int n_in,
                              void* d_out, int out_size) {
    const float* x   = (const float*)d_in[0];
    const int*   ei  = (const int*)d_in[1];   // JAX x64 disabled -> int32
    const float* W0  = (const float*)d_in[2];
    const float* b0  = (const float*)d_in[3];
    const float* W1  = (const float*)d_in[4];
    const float* b1  = (const float*)d_in[5];
    const float* Wf  = (const float*)d_in[6];
    const float* bf  = (const float*)d_in[7];
    float* out = (float*)d_out;

    int E = in_sizes[1] / 2;          // edge_index is [2, E]
    const int* src = ei;
    const int* dst = ei + E;

    int nb_n  = (NN + 255) / 256;
    int nb_c  = ((E + 3) / 4 + 255) / 256;
    int nb_s0 = (NN * FD / 4 + 255) / 256;
    int warps = (NN + NPW - 1) / NPW;            // 12500
    int nb_x  = (warps + 7) / 8;                 // 1563
    long long sthreads = (long long)E * 4;
    int nb_s  = (int)((sthreads + 255) / 256);

    // degree + normalization
    k_init_deg<<<nb_n, 256>>>();
    k_count<<<nb_c, 256>>>(dst, E);
    k_dinv<<<nb_n, 256>>>();

    // layer 0: scale only (transform moved after aggregation)
    k_scale0<<<nb_s0, 256>>>(x);
    k_scatter<<<nb_s, 256>>>(src, dst, E);

    // mid: apply W0 + relu, produce layer-1 messages
    k_mid<<<nb_x, 256>>>(W0, b0);
    k_scatter<<<nb_s, 256>>>(src, dst, E);

    // final: apply W1 + relu, then Wf + bf
    k_final<<<nb_x, 256>>>(W1, b1, Wf, bf, out);
}

// round 7
// speedup vs baseline: 1.3005x; 1.3005x over previous
#include <cuda_runtime.h>

#define NN 100000
#define FD 32
#define NPW 8

// Scratch (static device globals — no allocation in kernel_launch)
__device__ float g_scaled[NN * FD];  // messages (fp32), gather side
__device__ float g_agg[NN * FD];     // accumulator, seeded with self-loop
__device__ float g_dinv[NN];
__device__ int   g_deg[NN];

__global__ void k_init_deg() {
    int i = blockIdx.x * blockDim.x + threadIdx.x;
    if (i < NN) g_deg[i] = 1;  // self-loop contributes 1
}

__global__ void k_count(const int* __restrict__ dst, int E) {
    int t = blockIdx.x * blockDim.x + threadIdx.x;
    int e = t * 4;
    if (e + 3 < E) {
        int4 d = *reinterpret_cast<const int4*>(dst + e);
        atomicAdd(&g_deg[d.x], 1);
        atomicAdd(&g_deg[d.y], 1);
        atomicAdd(&g_deg[d.z], 1);
        atomicAdd(&g_deg[d.w], 1);
    } else {
        for (int i = e; i < E; i++) atomicAdd(&g_deg[dst[i]], 1);
    }
}

__global__ void k_dinv() {
    int i = blockIdx.x * blockDim.x + threadIdx.x;
    if (i < NN) g_dinv[i] = rsqrtf((float)g_deg[i]);
}

// s0 = dinv * x  (GCN linearity: weight multiply moved after aggregation).
// Writes messages + seeds accumulator (self-loop term folded).
__global__ void k_scale0(const float* __restrict__ x) {
    int g = blockIdx.x * blockDim.x + threadIdx.x;   // one float4 per thread
    if (g >= NN * FD / 4) return;
    int node = g >> 3;
    float dv = g_dinv[node];
    float4 v = *reinterpret_cast<const float4*>(x + (size_t)g * 4);
    v.x *= dv; v.y *= dv; v.z *= dv; v.w *= dv;
    *reinterpret_cast<float4*>(g_scaled + (size_t)g * 4) = v;
    *reinterpret_cast<float4*>(g_agg    + (size_t)g * 4) = v;
}

// Scatter: 8 lanes per edge, one float4 gather + one red.v4 each. No converts.
__global__ __launch_bounds__(256) void k_scatter(const int* __restrict__ src,
                                                 const int* __restrict__ dst,
                                                 int E) {
    long long t = (long long)blockIdx.x * 256 + threadIdx.x;
    int e = (int)(t >> 3);
    if (e >= E) return;
    int q = ((int)t & 7) << 2;   // feature offset 0,4,...,28

    int s = src[e];
    int d = dst[e];

    const float4 v = *reinterpret_cast<const float4*>(&g_scaled[(size_t)s * FD + q]);
    float* a = &g_agg[(size_t)d * FD + q];
    asm volatile("red.global.add.v4.f32 [%0], {%1, %2, %3, %4};"
                 :: "l"(a), "f"(v.x), "f"(v.y), "f"(v.z), "f"(v.w)
                 : "memory");
}

// Mid: Ph0 = dinv*agg0; h1 = relu(Ph0 @ W0 + b0); s1 = dinv*h1.
// Prefetches all NPW agg values (MLP=8) before the compute loop.
__global__ __launch_bounds__(256) void k_mid(const float* __restrict__ W0,
                                             const float* __restrict__ b0) {
    __shared__ float Ws[FD * FD];
    __shared__ float s_row[8][FD];
    int tid = threadIdx.x;
    int lane = tid & 31;
    int wb = tid >> 5;
    #pragma unroll
    for (int i = tid; i < FD * FD; i += 256) Ws[i] = W0[i];
    __syncthreads();

    float Wc[FD];
    #pragma unroll
    for (int k = 0; k < FD; k++) Wc[k] = Ws[k * FD + lane];  // conflict-free LDS
    float bl = b0[lane];

    int base = (blockIdx.x * 8 + wb) * NPW;
    if (base >= NN) return;

    float v[NPW], dvv[NPW];
    #pragma unroll
    for (int u = 0; u < NPW; u++) {                          // batched loads, MLP=8
        v[u]   = g_agg[(size_t)(base + u) * FD + lane];
        dvv[u] = __ldg(&g_dinv[base + u]);
    }

    #pragma unroll
    for (int u = 0; u < NPW; u++) {
        int node = base + u;
        float ph = dvv[u] * v[u];
        s_row[wb][lane] = ph;
        __syncwarp();
        const float4* r = reinterpret_cast<const float4*>(s_row[wb]);
        float acc = 0.0f;
        #pragma unroll
        for (int j = 0; j < FD / 4; j++) {
            float4 t4 = r[j];                                // broadcast LDS.128
            acc = fmaf(t4.x, Wc[4 * j + 0], acc);
            acc = fmaf(t4.y, Wc[4 * j + 1], acc);
            acc = fmaf(t4.z, Wc[4 * j + 2], acc);
            acc = fmaf(t4.w, Wc[4 * j + 3], acc);
        }
        __syncwarp();
        float s1 = dvv[u] * fmaxf(acc + bl, 0.0f);
        g_scaled[(size_t)node * FD + lane] = s1;
        g_agg[(size_t)node * FD + lane]    = s1;
    }
}

// Final: Ph1 = dinv*agg1; h2 = relu(Ph1 @ W1 + b1); out = h2 @ Wf + bf.
__global__ __launch_bounds__(256) void k_final(const float* __restrict__ W1,
                                               const float* __restrict__ b1,
                                               const float* __restrict__ Wf,
                                               const float* __restrict__ bf,
                                               float* __restrict__ out) {
    __shared__ float Ws1[FD * FD];
    __shared__ float Wsf[FD * FD];
    __shared__ float s_row[8][FD];
    int tid = threadIdx.x;
    int lane = tid & 31;
    int wb = tid >> 5;
    #pragma unroll
    for (int i = tid; i < FD * FD; i += 256) { Ws1[i] = W1[i]; Wsf[i] = Wf[i]; }
    __syncthreads();

    float Wc1[FD], Wcf[FD];
    #pragma unroll
    for (int k = 0; k < FD; k++) { Wc1[k] = Ws1[k * FD + lane]; Wcf[k] = Wsf[k * FD + lane]; }
    float b1l = b1[lane];
    float bfl = bf[lane];

    int base = (blockIdx.x * 8 + wb) * NPW;
    if (base >= NN) return;

    float v[NPW], dvv[NPW];
    #pragma unroll
    for (int u = 0; u < NPW; u++) {
        v[u]   = g_agg[(size_t)(base + u) * FD + lane];
        dvv[u] = __ldg(&g_dinv[base + u]);
    }

    #pragma unroll
    for (int u = 0; u < NPW; u++) {
        int node = base + u;
        float ph = dvv[u] * v[u];
        s_row[wb][lane] = ph;
        __syncwarp();
        const float4* r = reinterpret_cast<const float4*>(s_row[wb]);
        float acc = 0.0f;
        #pragma unroll
        for (int j = 0; j < FD / 4; j++) {
            float4 t4 = r[j];
            acc = fmaf(t4.x, Wc1[4 * j + 0], acc);
            acc = fmaf(t4.y, Wc1[4 * j + 1], acc);
            acc = fmaf(t4.z, Wc1[4 * j + 2], acc);
            acc = fmaf(t4.w, Wc1[4 * j + 3], acc);
        }
        __syncwarp();
        float h2 = fmaxf(acc + b1l, 0.0f);
        s_row[wb][lane] = h2;
        __syncwarp();
        float acc2 = bfl;
        #pragma unroll
        for (int j = 0; j < FD / 4; j++) {
            float4 t4 = r[j];
            acc2 = fmaf(t4.x, Wcf[4 * j + 0], acc2);
            acc2 = fmaf(t4.y, Wcf[4 * j + 1], acc2);
            acc2 = fmaf(t4.z, Wcf[4 * j + 2], acc2);
            acc2 = fmaf(t4.w, Wcf[4 * j + 3], acc2);
        }
        __syncwarp();
        out[(size_t)node * FD + lane] = acc2;
    }
}

extern "C" void kernel_launch(void* const* d_in, const int* in_sizes, int n_in,
                              void* d_out, int out_size) {
    const float* x   = (const float*)d_in[0];
    const int*   ei  = (const int*)d_in[1];   // JAX x64 disabled -> int32
    const float* W0  = (const float*)d_in[2];
    const float* b0  = (const float*)d_in[3];
    const float* W1  = (const float*)d_in[4];
    const float* b1  = (const float*)d_in[5];
    const float* Wf  = (const float*)d_in[6];
    const float* bf  = (const float*)d_in[7];
    float* out = (float*)d_out;

    int E = in_sizes[1] / 2;          // edge_index is [2, E]
    const int* src = ei;
    const int* dst = ei + E;

    int nb_n  = (NN + 255) / 256;
    int nb_c  = ((E + 3) / 4 + 255) / 256;
    int nb_s0 = (NN * FD / 4 + 255) / 256;
    int warps = (NN + NPW - 1) / NPW;            // 12500
    int nb_x  = (warps + 7) / 8;                 // 1563
    long long sthreads = (long long)E * 8;
    int nb_s  = (int)((sthreads + 255) / 256);

    // degree + normalization
    k_init_deg<<<nb_n, 256>>>();
    k_count<<<nb_c, 256>>>(dst, E);
    k_dinv<<<nb_n, 256>>>();

    // layer 0: scale only (W0 applied after aggregation)
    k_scale0<<<nb_s0, 256>>>(x);
    k_scatter<<<nb_s, 256>>>(src, dst, E);

    // mid: apply W0 + relu, produce layer-1 messages
    k_mid<<<nb_x, 256>>>(W0, b0);
    k_scatter<<<nb_s, 256>>>(src, dst, E);

    // final: apply W1 + relu, then Wf + bf
    k_final<<<nb_x, 256>>>(W1, b1, Wf, bf, out);
}